// round 1
// baseline (speedup 1.0000x reference)
#include <cuda_runtime.h>

// STN bilinear sampler.
// x: [32,256,256,32] f32 NHWC ; theta: [32,6] f32 ; out: [32,256,256,32] f32
// One thread handles 4 channels (one float4) of one output pixel.
// 8 threads per pixel -> each neighbor gather is 8 contiguous LDG.128 (128B).

#define B_ 32
#define H_ 256
#define W_ 256
#define C_ 32
#define CG_ (C_ / 4)   // 8 float4 groups per pixel

__global__ __launch_bounds__(256) void stn_kernel(
    const float* __restrict__ x,
    const float* __restrict__ theta,
    float* __restrict__ out)
{
    int gid = blockIdx.x * blockDim.x + threadIdx.x;   // [0, B*H*W*CG)
    int cg  = gid & (CG_ - 1);        // channel group 0..7
    int p   = gid >> 3;               // pixel id 0..B*H*W-1
    int b   = p >> 16;                // / (H*W) = /65536
    int pix = p & 0xFFFF;
    int oy  = pix >> 8;
    int ox  = pix & 0xFF;

    // affine params (uniform per batch; L1-cached)
    const float* t = theta + b * 6;
    float t0 = __ldg(t + 0), t1 = __ldg(t + 1), t2 = __ldg(t + 2);
    float t3 = __ldg(t + 3), t4 = __ldg(t + 4), t5 = __ldg(t + 5);

    // regular grid in [-1,1]: linspace step = 2/(N-1)
    float gx = -1.0f + (float)ox * (2.0f / 255.0f);
    float gy = -1.0f + (float)oy * (2.0f / 255.0f);

    float sx = 0.5f * (t0 * gx + t1 * gy + t2 + 1.0f) * (float)W_;
    float sy = 0.5f * (t3 * gx + t4 * gy + t5 + 1.0f) * (float)H_;

    // truncation toward zero, matching jnp astype(int32)
    int x0 = (int)sx;
    int y0 = (int)sy;
    int x1 = x0 + 1;
    int y1 = y0 + 1;

    int x0c = min(max(x0, 0), W_ - 1);
    int x1c = min(max(x1, 0), W_ - 1);
    int y0c = min(max(y0, 0), H_ - 1);
    int y1c = min(max(y1, 0), H_ - 1);

    float x0f = (float)x0c, x1f = (float)x1c;
    float y0f = (float)y0c, y1f = (float)y1c;

    float wa = (x1f - sx) * (y1f - sy);
    float wb = (x1f - sx) * (sy - y0f);
    float wc = (sx - x0f) * (y1f - sy);
    float wd = (sx - x0f) * (sy - y0f);

    // gather addresses, in float4 units (each input pixel = 8 float4)
    const float4* __restrict__ xf = (const float4*)x;
    int basep = b * (H_ * W_);
    int ia = (basep + y0c * W_ + x0c) * CG_ + cg;
    int ib = (basep + y1c * W_ + x0c) * CG_ + cg;
    int ic = (basep + y0c * W_ + x1c) * CG_ + cg;
    int id = (basep + y1c * W_ + x1c) * CG_ + cg;

    float4 pa = __ldg(xf + ia);
    float4 pb = __ldg(xf + ib);
    float4 pc = __ldg(xf + ic);
    float4 pd = __ldg(xf + id);

    float4 o;
    o.x = wa * pa.x + wb * pb.x + wc * pc.x + wd * pd.x;
    o.y = wa * pa.y + wb * pb.y + wc * pc.y + wd * pd.y;
    o.z = wa * pa.z + wb * pb.z + wc * pc.z + wd * pd.z;
    o.w = wa * pa.w + wb * pb.w + wc * pc.w + wd * pd.w;

    ((float4*)out)[gid] = o;
}

extern "C" void kernel_launch(void* const* d_in, const int* in_sizes, int n_in,
                              void* d_out, int out_size)
{
    const float* x     = (const float*)d_in[0];
    const float* theta = (const float*)d_in[1];
    float* out = (float*)d_out;

    int total_threads = B_ * H_ * W_ * CG_;   // 16,777,216
    int block = 256;
    int grid = total_threads / block;          // 65,536
    stn_kernel<<<grid, block>>>(x, theta, out);
}

// round 2
// speedup vs baseline: 1.4272x; 1.4272x over previous
#include <cuda_runtime.h>

// STN bilinear sampler, v2.
// x: [32,256,256,32] f32 NHWC ; theta: [32,6] f32 ; out: same shape as x.
// One thread handles one float4 channel-group of TWO output pixels (oy, oy+1).
// 8 threads per pixel -> each gather is a full 128B input-pixel line per LDG.

#define B_ 32
#define H_ 256
#define W_ 256
#define CG_ 8            // float4 groups per pixel (32 ch / 4)
#define STEP (2.0f / 255.0f)

__global__ __launch_bounds__(256) void stn_kernel(
    const float4* __restrict__ xf,
    const float* __restrict__ theta,
    float4* __restrict__ out)
{
    int gid = blockIdx.x * blockDim.x + threadIdx.x;   // [0, B*(H/2)*W*CG)
    int cg  = gid & 7;                 // channel group
    int ox  = (gid >> 3) & 255;
    int oyh = (gid >> 11) & 127;       // half-row index
    int b   = gid >> 18;               // batch
    int oy  = oyh << 1;

    // affine params (uniform per batch, L1 broadcast) — amortized over 2 pixels
    const float* t = theta + b * 6;
    float t0 = __ldg(t + 0), t1 = __ldg(t + 1), t2 = __ldg(t + 2);
    float t3 = __ldg(t + 3), t4 = __ldg(t + 4), t5 = __ldg(t + 5);

    float gx = -1.0f + (float)ox * STEP;
    int basep = b << 16;               // b * H*W

#pragma unroll
    for (int k = 0; k < 2; k++) {
        int oyk = oy + k;
        float gy = -1.0f + (float)oyk * STEP;

        // identical formula to reference: 0.5*(T·g + 1)*N, truncate toward zero
        float sx = 0.5f * (t0 * gx + t1 * gy + t2 + 1.0f) * (float)W_;
        float sy = 0.5f * (t3 * gx + t4 * gy + t5 + 1.0f) * (float)H_;

        int x0 = (int)sx;
        int y0 = (int)sy;

        int x0c = min(max(x0, 0), W_ - 1);
        int x1c = min(max(x0 + 1, 0), W_ - 1);
        int y0c = min(max(y0, 0), H_ - 1);
        int y1c = min(max(y0 + 1, 0), H_ - 1);

        float x0f = (float)x0c, x1f = (float)x1c;
        float y0f = (float)y0c, y1f = (float)y1c;

        float wa = (x1f - sx) * (y1f - sy);
        float wb = (x1f - sx) * (sy - y0f);
        float wc = (sx - x0f) * (y1f - sy);
        float wd = (sx - x0f) * (sy - y0f);

        // float4-unit indices; c/d columns derived from a/b via dx (0 or 8)
        int row0 = basep + (y0c << 8);
        int row1 = basep + (y1c << 8);
        int dx   = (x1c - x0c) << 3;
        int ia   = ((row0 + x0c) << 3) + cg;
        int ib   = ((row1 + x0c) << 3) + cg;

        float4 pa = __ldg(xf + ia);
        float4 pc = __ldg(xf + ia + dx);
        float4 pb = __ldg(xf + ib);
        float4 pd = __ldg(xf + ib + dx);

        float4 o;
        o.x = wa * pa.x + wb * pb.x + wc * pc.x + wd * pd.x;
        o.y = wa * pa.y + wb * pb.y + wc * pc.y + wd * pd.y;
        o.z = wa * pa.z + wb * pb.z + wc * pc.z + wd * pd.z;
        o.w = wa * pa.w + wb * pb.w + wc * pc.w + wd * pd.w;

        out[((basep + (oyk << 8) + ox) << 3) + cg] = o;
    }
}

extern "C" void kernel_launch(void* const* d_in, const int* in_sizes, int n_in,
                              void* d_out, int out_size)
{
    const float4* x    = (const float4*)d_in[0];
    const float* theta = (const float*)d_in[1];
    float4* out = (float4*)d_out;

    int total_threads = B_ * (H_ / 2) * W_ * CG_;   // 8,388,608
    int block = 256;
    int grid = total_threads / block;                // 32,768
    stn_kernel<<<grid, block>>>(x, theta, out);
}

// round 3
// speedup vs baseline: 1.6419x; 1.1504x over previous
#include <cuda_runtime.h>

// STN bilinear sampler, v3.
// x: [32,256,256,32] f32 NHWC ; theta: [32,6] f32 ; out: same shape.
// One thread: one float4 channel-group of FOUR output pixels (oy..oy+3).
// 8 threads/pixel -> each gather LDG.128 covers a full 128B input pixel line.
// Streaming stores (__stcs) keep L2 reserved for the gather working set.

#define B_ 32
#define H_ 256
#define W_ 256
#define CG_ 8            // float4 groups per pixel (32 ch / 4)
#define ROWS_ 4          // output rows per thread
#define STEP (2.0f / 255.0f)

__global__ __launch_bounds__(256) void stn_kernel(
    const float4* __restrict__ xf,
    const float* __restrict__ theta,
    float4* __restrict__ out)
{
    int gid = blockIdx.x * blockDim.x + threadIdx.x;   // [0, B*(H/4)*W*CG)
    int cg  = gid & 7;                 // channel group
    int ox  = (gid >> 3) & 255;
    int oyq = (gid >> 11) & 63;        // quarter-row index
    int b   = gid >> 17;               // batch
    int oy  = oyq << 2;

    // affine params (uniform per batch, L1 broadcast) — amortized over 4 pixels
    const float* t = theta + b * 6;
    float t0 = __ldg(t + 0), t1 = __ldg(t + 1), t2 = __ldg(t + 2);
    float t3 = __ldg(t + 3), t4 = __ldg(t + 4), t5 = __ldg(t + 5);

    float gx = -1.0f + (float)ox * STEP;
    int basep = b << 16;               // b * H*W
    int obase = ((basep + (oy << 8) + ox) << 3) + cg;

#pragma unroll
    for (int k = 0; k < ROWS_; k++) {
        float gy = -1.0f + (float)(oy + k) * STEP;

        // identical formula to reference: 0.5*(T·g + 1)*N, truncate toward zero
        float sx = 0.5f * (t0 * gx + t1 * gy + t2 + 1.0f) * (float)W_;
        float sy = 0.5f * (t3 * gx + t4 * gy + t5 + 1.0f) * (float)H_;

        int x0 = (int)sx;
        int y0 = (int)sy;

        int x0c = min(max(x0, 0), W_ - 1);
        int x1c = min(max(x0 + 1, 0), W_ - 1);
        int y0c = min(max(y0, 0), H_ - 1);
        int y1c = min(max(y0 + 1, 0), H_ - 1);

        float x0f = (float)x0c, x1f = (float)x1c;
        float y0f = (float)y0c, y1f = (float)y1c;

        float wa = (x1f - sx) * (y1f - sy);
        float wb = (x1f - sx) * (sy - y0f);
        float wc = (sx - x0f) * (y1f - sy);
        float wd = (sx - x0f) * (sy - y0f);

        // float4-unit indices; x1 column derived via dx (0 or 8)
        int dx = (x1c - x0c) << 3;
        int ia = ((basep + (y0c << 8) + x0c) << 3) + cg;
        int ib = ((basep + (y1c << 8) + x0c) << 3) + cg;

        float4 pa = __ldg(xf + ia);
        float4 pc = __ldg(xf + ia + dx);
        float4 pb = __ldg(xf + ib);
        float4 pd = __ldg(xf + ib + dx);

        float4 o;
        o.x = wa * pa.x + wb * pb.x + wc * pc.x + wd * pd.x;
        o.y = wa * pa.y + wb * pb.y + wc * pc.y + wd * pd.y;
        o.z = wa * pa.z + wb * pb.z + wc * pc.z + wd * pd.z;
        o.w = wa * pa.w + wb * pb.w + wc * pc.w + wd * pd.w;

        // streaming store: output is write-once, don't pollute L2
        __stcs(out + obase + (k << 11), o);   // k * W_ * CG_ = k*2048
    }
}

extern "C" void kernel_launch(void* const* d_in, const int* in_sizes, int n_in,
                              void* d_out, int out_size)
{
    const float4* x    = (const float4*)d_in[0];
    const float* theta = (const float*)d_in[1];
    float4* out = (float4*)d_out;

    int total_threads = B_ * (H_ / ROWS_) * W_ * CG_;   // 4,194,304
    int block = 256;
    int grid = total_threads / block;                    // 16,384
    stn_kernel<<<grid, block>>>(x, theta, out);
}